// round 10
// baseline (speedup 1.0000x reference)
#include <cuda_runtime.h>
#include <cstdint>

#define DEV __device__ __forceinline__

// ---------------- problem constants ----------------
static constexpr int BATCH = 32768;
static constexpr int DH    = 512;          // hidden per gate
static constexpr int KTOT  = 1024;         // D_IN + D_H
static constexpr int MT    = 128;          // batch rows per CTA (MMA N-dim)
static constexpr int HC    = 64;           // hidden cols per CTA per gate (MMA M = 4*64 = 256)
static constexpr int KC    = 32;           // K chunk
static constexpr int NCHUNK = KTOT / KC;   // 32
static constexpr int THREADS = 256;        // 8 warps
static constexpr int STAGES = 4;

// A (weights, pre-interleaved): 16 n-blocks x 2048B
static constexpr int A_STAGE_B = 16 * 2048;             // 32768
// B (activations, natural row-major): 128 rows x pitch 40 words
static constexpr int PB = 40;
static constexpr int B_STAGE_B = MT * PB * 4;           // 20480
static constexpr int STAGE_B   = A_STAGE_B + B_STAGE_B; // 53248
static constexpr uint32_t OFF_BIAS   = STAGES * STAGE_B;     // 212992
static constexpr uint32_t SMEM_BYTES = OFF_BIAS + 256 * 4;   // 214016

// ---------------- device scratch ----------------
// Pre-interleaved weights: [n-block 0..127][chunk 0..31][128 float4]
// float4 at f = s*32 + gid*4 + tig holds
//   { W[nb*16+gid][kc+k0], W[nb*16+gid+8][kc+k0], W[nb*16+gid][kc+k0+1], W[nb*16+gid+8][kc+k0+1] }
// with k0 = s*8 + 2*tig  (k-slot permutation: slot tig -> 2*tig, slot tig+4 -> 2*tig+1)
__device__ float g_Wint[4 * DH * KTOT];    // 8 MB

// ---------------- PTX helpers ----------------
DEV uint32_t smem_u32(const void* p) {
    uint32_t a;
    asm("{ .reg .u64 t; cvta.to.shared.u64 t, %1; cvt.u32.u64 %0, t; }" : "=r"(a) : "l"(p));
    return a;
}
DEV float tf32_rna(float v) {
    uint32_t u;
    asm("cvt.rna.tf32.f32 %0, %1;" : "=r"(u) : "f"(v));
    return __uint_as_float(u);
}
DEV void cpasync16(uint32_t dst, const void* src) {
    asm volatile("cp.async.cg.shared.global [%0], [%1], 16;" :: "r"(dst), "l"(src));
}
DEV void cp_commit() { asm volatile("cp.async.commit_group;" ::: "memory"); }
template <int N> DEV void cp_wait() { asm volatile("cp.async.wait_group %0;" :: "n"(N) : "memory"); }

// A quad comes straight from one LDS.128; B pair straight from one LDS.64.
DEV void mma_tf32(float* c, const float4& a, const float2& b) {
    asm volatile(
        "mma.sync.aligned.m16n8k8.row.col.f32.tf32.tf32.f32 "
        "{%0,%1,%2,%3}, {%4,%5,%6,%7}, {%8,%9}, {%0,%1,%2,%3};"
        : "+f"(c[0]), "+f"(c[1]), "+f"(c[2]), "+f"(c[3])
        : "r"(__float_as_uint(a.x)), "r"(__float_as_uint(a.y)),
          "r"(__float_as_uint(a.z)), "r"(__float_as_uint(a.w)),
          "r"(__float_as_uint(b.x)), "r"(__float_as_uint(b.y)));
}

DEV float sigm(float z)     { return __fdividef(1.0f, 1.0f + __expf(-z)); }
DEV float tanhfast(float z) { float t = __expf(2.0f * z); return 1.0f - __fdividef(2.0f, t + 1.0f); }

// ---------------- prep: transpose + tf32-rna + fragment-interleave weights ----------------
// grid (64 n-tiles of 32, 32 k-chunks), block (32, 8)
__global__ void lstm_prep(const float* __restrict__ Wx, const float* __restrict__ Wh) {
    __shared__ float t[32][33];            // t[k_local][n_local]
    const int tx = threadIdx.x, ty = threadIdx.y;
    const int nt = blockIdx.x * 32, kt = blockIdx.y * 32;
#pragma unroll
    for (int i = 0; i < 4; i++) {
        int k = kt + ty + i * 8;
        int n = nt + tx;
        float v = (k < 512) ? Wx[(size_t)k * 2048 + n] : Wh[(size_t)(k - 512) * 2048 + n];
        t[ty + i * 8][tx] = tf32_rna(v);
    }
    __syncthreads();
    const int tid = ty * 32 + tx;          // 0..255
    const int nbl = tid >> 7;              // local n-block (0..1)
    const int f   = tid & 127;
    const int s   = f >> 5, gid = (f >> 2) & 7, tig = f & 3;
    const int k0  = s * 8 + tig * 2;
    const int nl  = nbl * 16 + gid;
    float4 v;
    v.x = t[k0][nl];     v.y = t[k0][nl + 8];
    v.z = t[k0 + 1][nl]; v.w = t[k0 + 1][nl + 8];
    const int nb = blockIdx.x * 2 + nbl;
    ((float4*)g_Wint)[((size_t)nb * 32 + blockIdx.y) * 128 + f] = v;
}

// ---------------- main fused kernel ----------------
__global__ __launch_bounds__(THREADS, 1)
void lstm_main(const float* __restrict__ x, const float* __restrict__ Cin,
               const float* __restrict__ hin,
               const float* __restrict__ bx, const float* __restrict__ bh,
               float* __restrict__ out) {
    extern __shared__ float smem[];
    const uint32_t sb = smem_u32(smem);

    const int tid  = threadIdx.x;
    const int lane = tid & 31;
    const int wid  = tid >> 5;          // 0..7
    const int tig  = lane & 3;
    const int gid  = lane >> 2;
    const int wn   = wid & 3;           // hidden-col slab (16 cols per gate)
    const int wm   = wid >> 2;          // batch slab (64 rows)

    const int c0 = blockIdx.x * HC;     // hidden-col base (per gate)
    const int m0 = blockIdx.y * MT;     // batch base
    const int nbBase = c0 >> 4;         // n-block base within a gate (0..31 step 4)

    if (tid < 256) {                    // bias: [gate*64 + local col]
        int gate = tid >> 6, c = tid & 63;
        smem[OFF_BIAS / 4 + tid] = bx[gate * DH + c0 + c] + bh[gate * DH + c0 + c];
    }

    // ---- async stage loader ----
    auto issue = [&](int ck) {
        const int buf = ck & (STAGES - 1);
        const uint32_t Ao = sb + (uint32_t)(buf * STAGE_B);
        const uint32_t Bo = Ao + A_STAGE_B;
        const int kc0 = ck * KC;
        const float* Bbase = (kc0 < 512) ? (x + (size_t)m0 * 512 + kc0)
                                         : (hin + (size_t)m0 * 512 + (kc0 - 512));
        // A: 2048 granules of 16B (16 n-blocks x 128 float4), already fragment-ordered
#pragma unroll
        for (int i = 0; i < 8; i++) {
            int g = tid + i * THREADS;
            int bi = g >> 7, f = g & 127;
            int nb = (bi >> 2) * 32 + nbBase + (bi & 3);
            cpasync16(Ao + (uint32_t)g * 16,
                      g_Wint + (((size_t)nb * 32 + ck) * 128 + f) * 4);
        }
        // B: 1024 granules (128 rows x 8 x 16B), natural row-major, pitch 160B
#pragma unroll
        for (int i = 0; i < 4; i++) {
            int g = tid + i * THREADS;
            int r = g >> 3, j = g & 7;
            cpasync16(Bo + (uint32_t)(r * (PB * 4) + j * 16),
                      Bbase + (size_t)r * 512 + j * 4);
        }
    };

    float acc[4][4][2][4];               // [gate][mb][hh][reg]
#pragma unroll
    for (int a = 0; a < 4; a++)
#pragma unroll
        for (int b = 0; b < 4; b++)
#pragma unroll
            for (int c = 0; c < 2; c++)
#pragma unroll
                for (int r = 0; r < 4; r++) acc[a][b][c][r] = 0.0f;

    issue(0); cp_commit();
    issue(1); cp_commit();
    issue(2); cp_commit();

    // constant per-lane fragment offsets (floats)
    const int awl = wn * 512 + gid * 16 + tig * 4;        // + gate*2048 + s*128
    const int bwl = (wm * 64 + gid) * PB + tig * 2;       // + (mb*16+hh*8)*PB + s*8

    for (int ck = 0; ck < NCHUNK; ck++) {
        const int buf = ck & (STAGES - 1);
        const float* Aw = smem + (size_t)buf * (STAGE_B / 4) + awl;
        const float* Bw = smem + (size_t)buf * (STAGE_B / 4) + (A_STAGE_B / 4) + bwl;

        cp_wait<2>();
        __syncthreads();

#pragma unroll
        for (int s = 0; s < 4; s++) {
            float4 aq[4];
#pragma unroll
            for (int gate = 0; gate < 4; gate++)
                aq[gate] = *(const float4*)(Aw + gate * 2048 + s * 128);
            float2 bq[4][2];
#pragma unroll
            for (int mb = 0; mb < 4; mb++)
#pragma unroll
                for (int hh = 0; hh < 2; hh++)
                    bq[mb][hh] = *(const float2*)(Bw + (mb * 16 + hh * 8) * PB + s * 8);
#pragma unroll
            for (int gate = 0; gate < 4; gate++)
#pragma unroll
                for (int mb = 0; mb < 4; mb++)
#pragma unroll
                    for (int hh = 0; hh < 2; hh++)
                        mma_tf32(acc[gate][mb][hh], aq[gate], bq[mb][hh]);
        }

        if (ck + 3 < NCHUNK) issue(ck + 3);
        cp_commit();
    }

    // ---------------- fused LSTM epilogue ----------------
    // acc[gate][mb][hh][rh*2+e]: hidden col = c0 + wn*16 + rh*8 + gid,
    //                            batch row  = m0 + wm*64 + mb*16 + hh*8 + 2*tig + e
    const float* biasS = smem + OFF_BIAS / 4;
#pragma unroll
    for (int mb = 0; mb < 4; mb++) {
#pragma unroll
        for (int hh = 0; hh < 2; hh++) {
#pragma unroll
            for (int e = 0; e < 2; e++) {
                const int m = m0 + wm * 64 + mb * 16 + hh * 8 + 2 * tig + e;
#pragma unroll
                for (int rh = 0; rh < 2; rh++) {
                    const int cl = wn * 16 + rh * 8 + gid;   // local col 0..63
                    const int hc = c0 + cl;
                    const int j  = rh * 2 + e;
                    float zi = acc[0][mb][hh][j] + biasS[0 * 64 + cl];
                    float zf = acc[1][mb][hh][j] + biasS[1 * 64 + cl];
                    float zo = acc[2][mb][hh][j] + biasS[2 * 64 + cl];
                    float zg = acc[3][mb][hh][j] + biasS[3 * 64 + cl];
                    float gi = sigm(zi), gf = sigm(zf), go = sigm(zo), gg = tanhfast(zg);
                    float cv = Cin[(size_t)m * DH + hc];
                    float cn = gf * cv + gi * gg;
                    float hn = go * tanhfast(cn);
                    out[(size_t)m * DH + hc] = cn;
                    out[(size_t)BATCH * DH + (size_t)m * DH + hc] = hn;
                }
            }
        }
    }
}

// ---------------- launch ----------------
extern "C" void kernel_launch(void* const* d_in, const int* in_sizes, int n_in,
                              void* d_out, int out_size) {
    (void)in_sizes; (void)n_in; (void)out_size;
    const float* x  = (const float*)d_in[0];
    const float* C  = (const float*)d_in[1];
    const float* h  = (const float*)d_in[2];
    const float* Wx = (const float*)d_in[3];
    const float* bx = (const float*)d_in[4];
    const float* Wh = (const float*)d_in[5];
    const float* bh = (const float*)d_in[6];
    float* out = (float*)d_out;

    static bool attr_set = false;
    if (!attr_set) {
        cudaFuncSetAttribute(lstm_main, cudaFuncAttributeMaxDynamicSharedMemorySize, SMEM_BYTES);
        attr_set = true;
    }

    dim3 pgrid(2048 / 32, 1024 / 32);
    dim3 pblk(32, 8);
    lstm_prep<<<pgrid, pblk>>>(Wx, Wh);

    dim3 grid(DH / HC, BATCH / MT);     // (8 col tiles, 256 row tiles)
    lstm_main<<<grid, THREADS, SMEM_BYTES>>>(x, C, h, bx, bh, out);
}

// round 11
// speedup vs baseline: 1.0003x; 1.0003x over previous
#include <cuda_runtime.h>
#include <cstdint>

#define DEV __device__ __forceinline__

// ---------------- problem constants ----------------
static constexpr int BATCH = 32768;
static constexpr int DH    = 512;          // hidden per gate
static constexpr int KTOT  = 1024;         // D_IN + D_H
static constexpr int MT    = 128;          // batch rows per CTA (MMA N-dim)
static constexpr int HC    = 64;           // hidden cols per CTA per gate (MMA M = 4*64 = 256)
static constexpr int KC    = 32;           // K chunk
static constexpr int NCHUNK = KTOT / KC;   // 32
static constexpr int THREADS = 256;        // 8 warps
static constexpr int STAGES = 4;

// A (weights, pre-interleaved): 16 n-blocks x 2048B
static constexpr int A_STAGE_B = 16 * 2048;             // 32768
// B (activations, natural row-major): 128 rows x pitch 40 words
static constexpr int PB = 40;
static constexpr int B_STAGE_B = MT * PB * 4;           // 20480
static constexpr int STAGE_B   = A_STAGE_B + B_STAGE_B; // 53248
static constexpr uint32_t OFF_BIAS   = STAGES * STAGE_B;     // 212992
static constexpr uint32_t SMEM_BYTES = OFF_BIAS + 256 * 4;   // 214016

// ---------------- device scratch ----------------
// Pre-interleaved weights: [n-block 0..127][chunk 0..31][128 float4]
// float4 at f = s*32 + gid*4 + tig holds
//   { W[nb*16+gid][kc+k0], W[nb*16+gid+8][kc+k0], W[nb*16+gid][kc+k0+1], W[nb*16+gid+8][kc+k0+1] }
// with k0 = s*8 + 2*tig  (k-slot permutation: slot tig -> 2*tig, slot tig+4 -> 2*tig+1)
__device__ float g_Wint[4 * DH * KTOT];    // 8 MB

// ---------------- PTX helpers ----------------
DEV uint32_t smem_u32(const void* p) {
    uint32_t a;
    asm("{ .reg .u64 t; cvta.to.shared.u64 t, %1; cvt.u32.u64 %0, t; }" : "=r"(a) : "l"(p));
    return a;
}
DEV float tf32_rna(float v) {
    uint32_t u;
    asm("cvt.rna.tf32.f32 %0, %1;" : "=r"(u) : "f"(v));
    return __uint_as_float(u);
}
DEV void cpasync16(uint32_t dst, const void* src) {
    asm volatile("cp.async.cg.shared.global [%0], [%1], 16;" :: "r"(dst), "l"(src));
}
DEV void cp_commit() { asm volatile("cp.async.commit_group;" ::: "memory"); }
template <int N> DEV void cp_wait() { asm volatile("cp.async.wait_group %0;" :: "n"(N) : "memory"); }

// A quad comes straight from one LDS.128; B pair straight from one LDS.64.
DEV void mma_tf32(float* c, const float4& a, const float2& b) {
    asm volatile(
        "mma.sync.aligned.m16n8k8.row.col.f32.tf32.tf32.f32 "
        "{%0,%1,%2,%3}, {%4,%5,%6,%7}, {%8,%9}, {%0,%1,%2,%3};"
        : "+f"(c[0]), "+f"(c[1]), "+f"(c[2]), "+f"(c[3])
        : "r"(__float_as_uint(a.x)), "r"(__float_as_uint(a.y)),
          "r"(__float_as_uint(a.z)), "r"(__float_as_uint(a.w)),
          "r"(__float_as_uint(b.x)), "r"(__float_as_uint(b.y)));
}

DEV float sigm(float z)     { return __fdividef(1.0f, 1.0f + __expf(-z)); }
DEV float tanhfast(float z) { float t = __expf(2.0f * z); return 1.0f - __fdividef(2.0f, t + 1.0f); }

// ---------------- prep: transpose + tf32-rna + fragment-interleave weights ----------------
// grid (64 n-tiles of 32, 32 k-chunks), block (32, 8)
__global__ void lstm_prep(const float* __restrict__ Wx, const float* __restrict__ Wh) {
    __shared__ float t[32][33];            // t[k_local][n_local]
    const int tx = threadIdx.x, ty = threadIdx.y;
    const int nt = blockIdx.x * 32, kt = blockIdx.y * 32;
#pragma unroll
    for (int i = 0; i < 4; i++) {
        int k = kt + ty + i * 8;
        int n = nt + tx;
        float v = (k < 512) ? Wx[(size_t)k * 2048 + n] : Wh[(size_t)(k - 512) * 2048 + n];
        t[ty + i * 8][tx] = tf32_rna(v);
    }
    __syncthreads();
    const int tid = ty * 32 + tx;          // 0..255
    const int nbl = tid >> 7;              // local n-block (0..1)
    const int f   = tid & 127;
    const int s   = f >> 5, gid = (f >> 2) & 7, tig = f & 3;
    const int k0  = s * 8 + tig * 2;
    const int nl  = nbl * 16 + gid;
    float4 v;
    v.x = t[k0][nl];     v.y = t[k0][nl + 8];
    v.z = t[k0 + 1][nl]; v.w = t[k0 + 1][nl + 8];
    const int nb = blockIdx.x * 2 + nbl;
    ((float4*)g_Wint)[((size_t)nb * 32 + blockIdx.y) * 128 + f] = v;
}

// ---------------- main fused kernel ----------------
__global__ __launch_bounds__(THREADS, 1)
void lstm_main(const float* __restrict__ x, const float* __restrict__ Cin,
               const float* __restrict__ hin,
               const float* __restrict__ bx, const float* __restrict__ bh,
               float* __restrict__ out) {
    extern __shared__ float smem[];
    const uint32_t sb = smem_u32(smem);

    const int tid  = threadIdx.x;
    const int lane = tid & 31;
    const int wid  = tid >> 5;          // 0..7
    const int tig  = lane & 3;
    const int gid  = lane >> 2;
    const int wn   = wid & 3;           // hidden-col slab (16 cols per gate)
    const int wm   = wid >> 2;          // batch slab (64 rows)

    const int c0 = blockIdx.x * HC;     // hidden-col base (per gate)
    const int m0 = blockIdx.y * MT;     // batch base
    const int nbBase = c0 >> 4;         // n-block base within a gate (0..31 step 4)

    if (tid < 256) {                    // bias: [gate*64 + local col]
        int gate = tid >> 6, c = tid & 63;
        smem[OFF_BIAS / 4 + tid] = bx[gate * DH + c0 + c] + bh[gate * DH + c0 + c];
    }

    // ---- async stage loader ----
    auto issue = [&](int ck) {
        const int buf = ck & (STAGES - 1);
        const uint32_t Ao = sb + (uint32_t)(buf * STAGE_B);
        const uint32_t Bo = Ao + A_STAGE_B;
        const int kc0 = ck * KC;
        const float* Bbase = (kc0 < 512) ? (x + (size_t)m0 * 512 + kc0)
                                         : (hin + (size_t)m0 * 512 + (kc0 - 512));
        // A: 2048 granules of 16B (16 n-blocks x 128 float4), already fragment-ordered
#pragma unroll
        for (int i = 0; i < 8; i++) {
            int g = tid + i * THREADS;
            int bi = g >> 7, f = g & 127;
            int nb = (bi >> 2) * 32 + nbBase + (bi & 3);
            cpasync16(Ao + (uint32_t)g * 16,
                      g_Wint + (((size_t)nb * 32 + ck) * 128 + f) * 4);
        }
        // B: 1024 granules (128 rows x 8 x 16B), natural row-major, pitch 160B
#pragma unroll
        for (int i = 0; i < 4; i++) {
            int g = tid + i * THREADS;
            int r = g >> 3, j = g & 7;
            cpasync16(Bo + (uint32_t)(r * (PB * 4) + j * 16),
                      Bbase + (size_t)r * 512 + j * 4);
        }
    };

    float acc[4][4][2][4];               // [gate][mb][hh][reg]
#pragma unroll
    for (int a = 0; a < 4; a++)
#pragma unroll
        for (int b = 0; b < 4; b++)
#pragma unroll
            for (int c = 0; c < 2; c++)
#pragma unroll
                for (int r = 0; r < 4; r++) acc[a][b][c][r] = 0.0f;

    issue(0); cp_commit();
    issue(1); cp_commit();
    issue(2); cp_commit();

    // constant per-lane fragment offsets (floats)
    const int awl = wn * 512 + gid * 16 + tig * 4;        // + gate*2048 + s*128
    const int bwl = (wm * 64 + gid) * PB + tig * 2;       // + (mb*16+hh*8)*PB + s*8

    for (int ck = 0; ck < NCHUNK; ck++) {
        const int buf = ck & (STAGES - 1);
        const float* Aw = smem + (size_t)buf * (STAGE_B / 4) + awl;
        const float* Bw = smem + (size_t)buf * (STAGE_B / 4) + (A_STAGE_B / 4) + bwl;

        cp_wait<2>();
        __syncthreads();

#pragma unroll
        for (int s = 0; s < 4; s++) {
            float4 aq[4];
#pragma unroll
            for (int gate = 0; gate < 4; gate++)
                aq[gate] = *(const float4*)(Aw + gate * 2048 + s * 128);
            float2 bq[4][2];
#pragma unroll
            for (int mb = 0; mb < 4; mb++)
#pragma unroll
                for (int hh = 0; hh < 2; hh++)
                    bq[mb][hh] = *(const float2*)(Bw + (mb * 16 + hh * 8) * PB + s * 8);
#pragma unroll
            for (int gate = 0; gate < 4; gate++)
#pragma unroll
                for (int mb = 0; mb < 4; mb++)
#pragma unroll
                    for (int hh = 0; hh < 2; hh++)
                        mma_tf32(acc[gate][mb][hh], aq[gate], bq[mb][hh]);
        }

        if (ck + 3 < NCHUNK) issue(ck + 3);
        cp_commit();
    }

    // ---------------- fused LSTM epilogue ----------------
    // acc[gate][mb][hh][rh*2+e]: hidden col = c0 + wn*16 + rh*8 + gid,
    //                            batch row  = m0 + wm*64 + mb*16 + hh*8 + 2*tig + e
    const float* biasS = smem + OFF_BIAS / 4;
#pragma unroll
    for (int mb = 0; mb < 4; mb++) {
#pragma unroll
        for (int hh = 0; hh < 2; hh++) {
#pragma unroll
            for (int e = 0; e < 2; e++) {
                const int m = m0 + wm * 64 + mb * 16 + hh * 8 + 2 * tig + e;
#pragma unroll
                for (int rh = 0; rh < 2; rh++) {
                    const int cl = wn * 16 + rh * 8 + gid;   // local col 0..63
                    const int hc = c0 + cl;
                    const int j  = rh * 2 + e;
                    float zi = acc[0][mb][hh][j] + biasS[0 * 64 + cl];
                    float zf = acc[1][mb][hh][j] + biasS[1 * 64 + cl];
                    float zo = acc[2][mb][hh][j] + biasS[2 * 64 + cl];
                    float zg = acc[3][mb][hh][j] + biasS[3 * 64 + cl];
                    float gi = sigm(zi), gf = sigm(zf), go = sigm(zo), gg = tanhfast(zg);
                    float cv = Cin[(size_t)m * DH + hc];
                    float cn = gf * cv + gi * gg;
                    float hn = go * tanhfast(cn);
                    out[(size_t)m * DH + hc] = cn;
                    out[(size_t)BATCH * DH + (size_t)m * DH + hc] = hn;
                }
            }
        }
    }
}

// ---------------- launch ----------------
extern "C" void kernel_launch(void* const* d_in, const int* in_sizes, int n_in,
                              void* d_out, int out_size) {
    (void)in_sizes; (void)n_in; (void)out_size;
    const float* x  = (const float*)d_in[0];
    const float* C  = (const float*)d_in[1];
    const float* h  = (const float*)d_in[2];
    const float* Wx = (const float*)d_in[3];
    const float* bx = (const float*)d_in[4];
    const float* Wh = (const float*)d_in[5];
    const float* bh = (const float*)d_in[6];
    float* out = (float*)d_out;

    static bool attr_set = false;
    if (!attr_set) {
        cudaFuncSetAttribute(lstm_main, cudaFuncAttributeMaxDynamicSharedMemorySize, SMEM_BYTES);
        attr_set = true;
    }

    dim3 pgrid(2048 / 32, 1024 / 32);
    dim3 pblk(32, 8);
    lstm_prep<<<pgrid, pblk>>>(Wx, Wh);

    dim3 grid(DH / HC, BATCH / MT);     // (8 col tiles, 256 row tiles)
    lstm_main<<<grid, THREADS, SMEM_BYTES>>>(x, C, h, bx, bh, out);
}

// round 12
// speedup vs baseline: 1.0009x; 1.0005x over previous
#include <cuda_runtime.h>
#include <cstdint>

#define DEV __device__ __forceinline__

// ---------------- problem constants ----------------
static constexpr int BATCH = 32768;
static constexpr int DH    = 512;          // hidden per gate
static constexpr int KTOT  = 1024;         // D_IN + D_H
static constexpr int MT    = 128;          // batch rows per CTA (MMA N-dim)
static constexpr int HC    = 64;           // hidden cols per CTA per gate (MMA M = 4*64 = 256)
static constexpr int KC    = 32;           // K chunk
static constexpr int NCHUNK = KTOT / KC;   // 32
static constexpr int THREADS = 256;        // 8 warps
static constexpr int STAGES = 4;

// A (weights, pre-interleaved): 16 n-blocks x 2048B
static constexpr int A_STAGE_B = 16 * 2048;             // 32768
// B (activations, natural row-major): 128 rows x pitch 40 words
static constexpr int PB = 40;
static constexpr int B_STAGE_B = MT * PB * 4;           // 20480
static constexpr int STAGE_B   = A_STAGE_B + B_STAGE_B; // 53248
static constexpr uint32_t OFF_BIAS   = STAGES * STAGE_B;     // 212992
static constexpr uint32_t SMEM_BYTES = OFF_BIAS + 256 * 4;   // 214016

// ---------------- device scratch ----------------
// Pre-interleaved weights: [n-block 0..127][chunk 0..31][128 float4]
// float4 at f = s*32 + gid*4 + tig holds
//   { W[nb*16+gid][kc+k0], W[nb*16+gid+8][kc+k0], W[nb*16+gid][kc+k0+1], W[nb*16+gid+8][kc+k0+1] }
// with k0 = s*8 + 2*tig  (k-slot permutation: slot tig -> 2*tig, slot tig+4 -> 2*tig+1)
__device__ float g_Wint[4 * DH * KTOT];    // 8 MB

// ---------------- PTX helpers ----------------
DEV uint32_t smem_u32(const void* p) {
    uint32_t a;
    asm("{ .reg .u64 t; cvta.to.shared.u64 t, %1; cvt.u32.u64 %0, t; }" : "=r"(a) : "l"(p));
    return a;
}
DEV float tf32_rna(float v) {
    uint32_t u;
    asm("cvt.rna.tf32.f32 %0, %1;" : "=r"(u) : "f"(v));
    return __uint_as_float(u);
}
DEV void cpasync16(uint32_t dst, const void* src) {
    asm volatile("cp.async.cg.shared.global [%0], [%1], 16;" :: "r"(dst), "l"(src));
}
DEV void cp_commit() { asm volatile("cp.async.commit_group;" ::: "memory"); }
template <int N> DEV void cp_wait() { asm volatile("cp.async.wait_group %0;" :: "n"(N) : "memory"); }

// A quad comes straight from one LDS.128; B pair straight from one LDS.64.
DEV void mma_tf32(float* c, const float4& a, const float2& b) {
    asm volatile(
        "mma.sync.aligned.m16n8k8.row.col.f32.tf32.tf32.f32 "
        "{%0,%1,%2,%3}, {%4,%5,%6,%7}, {%8,%9}, {%0,%1,%2,%3};"
        : "+f"(c[0]), "+f"(c[1]), "+f"(c[2]), "+f"(c[3])
        : "r"(__float_as_uint(a.x)), "r"(__float_as_uint(a.y)),
          "r"(__float_as_uint(a.z)), "r"(__float_as_uint(a.w)),
          "r"(__float_as_uint(b.x)), "r"(__float_as_uint(b.y)));
}

DEV float sigm(float z)     { return __fdividef(1.0f, 1.0f + __expf(-z)); }
DEV float tanhfast(float z) { float t = __expf(2.0f * z); return 1.0f - __fdividef(2.0f, t + 1.0f); }

// ---------------- prep: transpose + tf32-rna + fragment-interleave weights ----------------
// grid (64 n-tiles of 32, 32 k-chunks), block (32, 8)
__global__ void lstm_prep(const float* __restrict__ Wx, const float* __restrict__ Wh) {
    __shared__ float t[32][33];            // t[k_local][n_local]
    const int tx = threadIdx.x, ty = threadIdx.y;
    const int nt = blockIdx.x * 32, kt = blockIdx.y * 32;
#pragma unroll
    for (int i = 0; i < 4; i++) {
        int k = kt + ty + i * 8;
        int n = nt + tx;
        float v = (k < 512) ? Wx[(size_t)k * 2048 + n] : Wh[(size_t)(k - 512) * 2048 + n];
        t[ty + i * 8][tx] = tf32_rna(v);
    }
    __syncthreads();
    const int tid = ty * 32 + tx;          // 0..255
    const int nbl = tid >> 7;              // local n-block (0..1)
    const int f   = tid & 127;
    const int s   = f >> 5, gid = (f >> 2) & 7, tig = f & 3;
    const int k0  = s * 8 + tig * 2;
    const int nl  = nbl * 16 + gid;
    float4 v;
    v.x = t[k0][nl];     v.y = t[k0][nl + 8];
    v.z = t[k0 + 1][nl]; v.w = t[k0 + 1][nl + 8];
    const int nb = blockIdx.x * 2 + nbl;
    ((float4*)g_Wint)[((size_t)nb * 32 + blockIdx.y) * 128 + f] = v;
}

// ---------------- main fused kernel ----------------
__global__ __launch_bounds__(THREADS, 1)
void lstm_main(const float* __restrict__ x, const float* __restrict__ Cin,
               const float* __restrict__ hin,
               const float* __restrict__ bx, const float* __restrict__ bh,
               float* __restrict__ out) {
    extern __shared__ float smem[];
    const uint32_t sb = smem_u32(smem);

    const int tid  = threadIdx.x;
    const int lane = tid & 31;
    const int wid  = tid >> 5;          // 0..7
    const int tig  = lane & 3;
    const int gid  = lane >> 2;
    const int wn   = wid & 3;           // hidden-col slab (16 cols per gate)
    const int wm   = wid >> 2;          // batch slab (64 rows)

    const int c0 = blockIdx.x * HC;     // hidden-col base (per gate)
    const int m0 = blockIdx.y * MT;     // batch base
    const int nbBase = c0 >> 4;         // n-block base within a gate (0..31 step 4)

    if (tid < 256) {                    // bias: [gate*64 + local col]
        int gate = tid >> 6, c = tid & 63;
        smem[OFF_BIAS / 4 + tid] = bx[gate * DH + c0 + c] + bh[gate * DH + c0 + c];
    }

    // ---- async stage loader ----
    auto issue = [&](int ck) {
        const int buf = ck & (STAGES - 1);
        const uint32_t Ao = sb + (uint32_t)(buf * STAGE_B);
        const uint32_t Bo = Ao + A_STAGE_B;
        const int kc0 = ck * KC;
        const float* Bbase = (kc0 < 512) ? (x + (size_t)m0 * 512 + kc0)
                                         : (hin + (size_t)m0 * 512 + (kc0 - 512));
        // A: 2048 granules of 16B (16 n-blocks x 128 float4), already fragment-ordered
#pragma unroll
        for (int i = 0; i < 8; i++) {
            int g = tid + i * THREADS;
            int bi = g >> 7, f = g & 127;
            int nb = (bi >> 2) * 32 + nbBase + (bi & 3);
            cpasync16(Ao + (uint32_t)g * 16,
                      g_Wint + (((size_t)nb * 32 + ck) * 128 + f) * 4);
        }
        // B: 1024 granules (128 rows x 8 x 16B), natural row-major, pitch 160B
#pragma unroll
        for (int i = 0; i < 4; i++) {
            int g = tid + i * THREADS;
            int r = g >> 3, j = g & 7;
            cpasync16(Bo + (uint32_t)(r * (PB * 4) + j * 16),
                      Bbase + (size_t)r * 512 + j * 4);
        }
    };

    float acc[4][4][2][4];               // [gate][mb][hh][reg]
#pragma unroll
    for (int a = 0; a < 4; a++)
#pragma unroll
        for (int b = 0; b < 4; b++)
#pragma unroll
            for (int c = 0; c < 2; c++)
#pragma unroll
                for (int r = 0; r < 4; r++) acc[a][b][c][r] = 0.0f;

    issue(0); cp_commit();
    issue(1); cp_commit();
    issue(2); cp_commit();

    // constant per-lane fragment offsets (floats)
    const int awl = wn * 512 + gid * 16 + tig * 4;        // + gate*2048 + s*128
    const int bwl = (wm * 64 + gid) * PB + tig * 2;       // + (mb*16+hh*8)*PB + s*8

    for (int ck = 0; ck < NCHUNK; ck++) {
        const int buf = ck & (STAGES - 1);
        const float* Aw = smem + (size_t)buf * (STAGE_B / 4) + awl;
        const float* Bw = smem + (size_t)buf * (STAGE_B / 4) + (A_STAGE_B / 4) + bwl;

        cp_wait<2>();
        __syncthreads();

#pragma unroll
        for (int s = 0; s < 4; s++) {
            float4 aq[4];
#pragma unroll
            for (int gate = 0; gate < 4; gate++)
                aq[gate] = *(const float4*)(Aw + gate * 2048 + s * 128);
            float2 bq[4][2];
#pragma unroll
            for (int mb = 0; mb < 4; mb++)
#pragma unroll
                for (int hh = 0; hh < 2; hh++)
                    bq[mb][hh] = *(const float2*)(Bw + (mb * 16 + hh * 8) * PB + s * 8);
#pragma unroll
            for (int gate = 0; gate < 4; gate++)
#pragma unroll
                for (int mb = 0; mb < 4; mb++)
#pragma unroll
                    for (int hh = 0; hh < 2; hh++)
                        mma_tf32(acc[gate][mb][hh], aq[gate], bq[mb][hh]);
        }

        if (ck + 3 < NCHUNK) issue(ck + 3);
        cp_commit();
    }

    // ---------------- fused LSTM epilogue ----------------
    // acc[gate][mb][hh][rh*2+e]: hidden col = c0 + wn*16 + rh*8 + gid,
    //                            batch row  = m0 + wm*64 + mb*16 + hh*8 + 2*tig + e
    const float* biasS = smem + OFF_BIAS / 4;
#pragma unroll
    for (int mb = 0; mb < 4; mb++) {
#pragma unroll
        for (int hh = 0; hh < 2; hh++) {
#pragma unroll
            for (int e = 0; e < 2; e++) {
                const int m = m0 + wm * 64 + mb * 16 + hh * 8 + 2 * tig + e;
#pragma unroll
                for (int rh = 0; rh < 2; rh++) {
                    const int cl = wn * 16 + rh * 8 + gid;   // local col 0..63
                    const int hc = c0 + cl;
                    const int j  = rh * 2 + e;
                    float zi = acc[0][mb][hh][j] + biasS[0 * 64 + cl];
                    float zf = acc[1][mb][hh][j] + biasS[1 * 64 + cl];
                    float zo = acc[2][mb][hh][j] + biasS[2 * 64 + cl];
                    float zg = acc[3][mb][hh][j] + biasS[3 * 64 + cl];
                    float gi = sigm(zi), gf = sigm(zf), go = sigm(zo), gg = tanhfast(zg);
                    float cv = Cin[(size_t)m * DH + hc];
                    float cn = gf * cv + gi * gg;
                    float hn = go * tanhfast(cn);
                    out[(size_t)m * DH + hc] = cn;
                    out[(size_t)BATCH * DH + (size_t)m * DH + hc] = hn;
                }
            }
        }
    }
}

// ---------------- launch ----------------
extern "C" void kernel_launch(void* const* d_in, const int* in_sizes, int n_in,
                              void* d_out, int out_size) {
    (void)in_sizes; (void)n_in; (void)out_size;
    const float* x  = (const float*)d_in[0];
    const float* C  = (const float*)d_in[1];
    const float* h  = (const float*)d_in[2];
    const float* Wx = (const float*)d_in[3];
    const float* bx = (const float*)d_in[4];
    const float* Wh = (const float*)d_in[5];
    const float* bh = (const float*)d_in[6];
    float* out = (float*)d_out;

    static bool attr_set = false;
    if (!attr_set) {
        cudaFuncSetAttribute(lstm_main, cudaFuncAttributeMaxDynamicSharedMemorySize, SMEM_BYTES);
        attr_set = true;
    }

    dim3 pgrid(2048 / 32, 1024 / 32);
    dim3 pblk(32, 8);
    lstm_prep<<<pgrid, pblk>>>(Wx, Wh);

    dim3 grid(DH / HC, BATCH / MT);     // (8 col tiles, 256 row tiles)
    lstm_main<<<grid, THREADS, SMEM_BYTES>>>(x, C, h, bx, bh, out);
}